// round 7
// baseline (speedup 1.0000x reference)
#include <cuda_runtime.h>
#include <math.h>

#define B_TOTAL 131072
#define Hh 128
#define Dd 256
#define Ee 128
#define G3H 384
#define MT 32
#define NTHR 256

typedef unsigned long long u64;

__device__ __forceinline__ u64 pack2(float lo, float hi) {
    u64 r;
    asm("mov.b64 %0,{%1,%2};" : "=l"(r)
        : "r"(__float_as_uint(lo)), "r"(__float_as_uint(hi)));
    return r;
}
__device__ __forceinline__ u64 bcast2(float x) {
    u64 r;
    asm("mov.b64 %0,{%1,%1};" : "=l"(r) : "r"(__float_as_uint(x)));
    return r;
}
__device__ __forceinline__ void ffma2(u64& d, u64 a, u64 b) {
    asm("fma.rn.f32x2 %0,%1,%2,%3;" : "=l"(d) : "l"(a), "l"(b), "l"(d));
}
__device__ __forceinline__ void unpk2(u64 v, float& a, float& b) {
    unsigned lo, hi;
    asm("mov.b64 {%0,%1},%2;" : "=r"(lo), "=r"(hi) : "l"(v));
    a = __uint_as_float(lo); b = __uint_as_float(hi);
}

// Transposed GRU weights (k-major [E][3H]) — device scratch, no allocation.
__device__ float g_wihT[Ee * G3H];
__device__ float g_whhT[Hh * G3H];

__global__ void transpose_gru_kernel(const float* __restrict__ wih,
                                     const float* __restrict__ whh) {
    int idx = blockIdx.x * blockDim.x + threadIdx.x;
    if (idx < Ee * G3H) {
        int e = idx / G3H, j = idx % G3H;
        g_wihT[idx] = wih[j * Ee + e];
        g_whhT[idx] = whh[j * Hh + e];
    }
}

// ---------------------------------------------------------------------------
// evolve: one RK4 (3/8 rule) step per row. 32 rows/CTA, 8 warps, 4 rows/warp.
// Round-1 structure (warp-private smem rows, no in-loop block barriers except
// one alignment barrier per stage before mm2), FFMA2-packed inner loops.
// ---------------------------------------------------------------------------
#define EV_SMEM_FLOATS 50080
__global__ void __launch_bounds__(NTHR, 1) evolve_kernel(
    const float* __restrict__ hidden, const float* __restrict__ dts,
    const float* __restrict__ w1, const float* __restrict__ b1,
    const float* __restrict__ lnw, const float* __restrict__ lnb,
    const float* __restrict__ w2, const float* __restrict__ b2,
    float* __restrict__ evolved)
{
    extern __shared__ float sm[];
    float* w1_s  = sm;              // 32768 floats (128KB), resident
    float* h_s   = sm + 32768;      // 32x128
    float* arg_s = sm + 36864;      // 32x128
    float* a_s   = sm + 40960;      // 32x256
    float* b1_s  = sm + 49152;      // 256
    float* lnw_s = sm + 49408;      // 256
    float* lnb_s = sm + 49664;      // 256
    float* b2_s  = sm + 49920;      // 128
    float* dt_s  = sm + 50048;      // 32

    const int tid  = threadIdx.x;
    const int lane = tid & 31;
    const int wrp  = tid >> 5;
    const int r0   = wrp * 4;                       // local row base (4 rows/warp)
    const size_t row0 = (size_t)blockIdx.x * MT;

    // ---- stage weights + tile ----
    {
        const float4* src = reinterpret_cast<const float4*>(w1);
        float4* dst = reinterpret_cast<float4*>(w1_s);
        #pragma unroll
        for (int t = 0; t < 32; ++t) dst[tid + t * NTHR] = src[tid + t * NTHR];
    }
    {
        const float4* src = reinterpret_cast<const float4*>(hidden + row0 * Hh);
        float4* dh = reinterpret_cast<float4*>(h_s);
        float4* da = reinterpret_cast<float4*>(arg_s);
        #pragma unroll
        for (int t = 0; t < 4; ++t) {
            float4 v = src[tid + t * NTHR];
            dh[tid + t * NTHR] = v;
            da[tid + t * NTHR] = v;
        }
    }
    if (tid < 256) { b1_s[tid] = b1[tid]; lnw_s[tid] = lnw[tid]; lnb_s[tid] = lnb[tid]; }
    if (tid < 128) b2_s[tid] = b2[tid];
    if (tid < 32)  dt_s[tid] = fmaxf(dts[row0 + tid], 0.0f);
    __syncthreads();

    float k1r[4][4], k2r[4][4], accr[4][4];

    #pragma unroll 1
    for (int s = 0; s < 4; ++s) {
        // ---- mm1: u[4 rows][8 cols] = arg @ w1 + b1 (FFMA2-packed) ----
        u64 u2[4][4];
        #pragma unroll
        for (int i = 0; i < 4; ++i)
            #pragma unroll
            for (int p = 0; p < 4; ++p)
                u2[i][p] = pack2(b1_s[lane * 8 + 2 * p], b1_s[lane * 8 + 2 * p + 1]);

        const ulonglong2* w1u = reinterpret_cast<const ulonglong2*>(w1_s);
        #pragma unroll 2
        for (int k = 0; k < Hh; k += 4) {
            float4 av[4];
            #pragma unroll
            for (int i = 0; i < 4; ++i)
                av[i] = *reinterpret_cast<const float4*>(arg_s + (r0 + i) * Hh + k);
            #pragma unroll
            for (int kk = 0; kk < 4; ++kk) {
                ulonglong2 W0 = w1u[(k + kk) * 64 + lane * 2];
                ulonglong2 W1 = w1u[(k + kk) * 64 + lane * 2 + 1];
                #pragma unroll
                for (int i = 0; i < 4; ++i) {
                    float a = (kk == 0) ? av[i].x : (kk == 1) ? av[i].y
                            : (kk == 2) ? av[i].z : av[i].w;
                    u64 aa = bcast2(a);
                    ffma2(u2[i][0], aa, W0.x);
                    ffma2(u2[i][1], aa, W0.y);
                    ffma2(u2[i][2], aa, W1.x);
                    ffma2(u2[i][3], aa, W1.y);
                }
            }
        }

        // ---- LayerNorm + exact GELU, a -> smem ----
        #pragma unroll
        for (int i = 0; i < 4; ++i) {
            float uv[8];
            #pragma unroll
            for (int p = 0; p < 4; ++p) unpk2(u2[i][p], uv[2 * p], uv[2 * p + 1]);
            float s1 = 0.f, s2 = 0.f;
            #pragma unroll
            for (int j = 0; j < 8; ++j) { s1 += uv[j]; s2 += uv[j] * uv[j]; }
            #pragma unroll
            for (int off = 16; off >= 1; off >>= 1) {
                s1 += __shfl_xor_sync(0xffffffffu, s1, off);
                s2 += __shfl_xor_sync(0xffffffffu, s2, off);
            }
            float mu   = s1 * (1.0f / Dd);
            float var  = s2 * (1.0f / Dd) - mu * mu;
            float rstd = rsqrtf(var + 1e-5f);
            #pragma unroll
            for (int j = 0; j < 8; ++j) {
                int c = lane * 8 + j;
                float v = (uv[j] - mu) * rstd * lnw_s[c] + lnb_s[c];
                a_s[(r0 + i) * Dd + c] = v * normcdff(v);   // exact gelu
            }
        }
        // align warps so the 8-warp shared w2 L2 stream dedups in L1
        __syncthreads();

        // ---- mm2: kv[4 rows][4 cols] = a @ w2 + b2 (w2 streamed, FFMA2) ----
        u64 kv2[4][2];
        #pragma unroll
        for (int i = 0; i < 4; ++i) {
            kv2[i][0] = pack2(b2_s[lane * 4],     b2_s[lane * 4 + 1]);
            kv2[i][1] = pack2(b2_s[lane * 4 + 2], b2_s[lane * 4 + 3]);
        }

        const ulonglong2* w2u = reinterpret_cast<const ulonglong2*>(w2);
        #pragma unroll 2
        for (int d = 0; d < Dd; d += 4) {
            float4 av[4];
            #pragma unroll
            for (int i = 0; i < 4; ++i)
                av[i] = *reinterpret_cast<const float4*>(a_s + (r0 + i) * Dd + d);
            #pragma unroll
            for (int dd = 0; dd < 4; ++dd) {
                ulonglong2 W = __ldg(w2u + (d + dd) * 32 + lane);
                #pragma unroll
                for (int i = 0; i < 4; ++i) {
                    float a = (dd == 0) ? av[i].x : (dd == 1) ? av[i].y
                            : (dd == 2) ? av[i].z : av[i].w;
                    u64 aa = bcast2(a);
                    ffma2(kv2[i][0], aa, W.x);
                    ffma2(kv2[i][1], aa, W.y);
                }
            }
        }

        // ---- RK4 stage combine (warp-private rows) ----
        float kv[4][4];
        #pragma unroll
        for (int i = 0; i < 4; ++i) {
            unpk2(kv2[i][0], kv[i][0], kv[i][1]);
            unpk2(kv2[i][1], kv[i][2], kv[i][3]);
        }

        if (s == 0) {
            #pragma unroll
            for (int i = 0; i < 4; ++i) {
                float dt = dt_s[r0 + i];
                #pragma unroll
                for (int j = 0; j < 4; ++j) {
                    int c = lane * 4 + j;
                    k1r[i][j] = kv[i][j];
                    accr[i][j] = kv[i][j];
                    arg_s[(r0 + i) * Hh + c] =
                        h_s[(r0 + i) * Hh + c] + dt * (kv[i][j] * (1.0f / 3.0f));
                }
            }
        } else if (s == 1) {
            #pragma unroll
            for (int i = 0; i < 4; ++i) {
                float dt = dt_s[r0 + i];
                #pragma unroll
                for (int j = 0; j < 4; ++j) {
                    int c = lane * 4 + j;
                    k2r[i][j] = kv[i][j];
                    accr[i][j] += 3.0f * kv[i][j];
                    arg_s[(r0 + i) * Hh + c] =
                        h_s[(r0 + i) * Hh + c] + dt * (kv[i][j] - k1r[i][j] * (1.0f / 3.0f));
                }
            }
        } else if (s == 2) {
            #pragma unroll
            for (int i = 0; i < 4; ++i) {
                float dt = dt_s[r0 + i];
                #pragma unroll
                for (int j = 0; j < 4; ++j) {
                    int c = lane * 4 + j;
                    accr[i][j] += 3.0f * kv[i][j];
                    arg_s[(r0 + i) * Hh + c] =
                        h_s[(r0 + i) * Hh + c] + dt * (k1r[i][j] - k2r[i][j] + kv[i][j]);
                }
            }
        } else {
            #pragma unroll
            for (int i = 0; i < 4; ++i) {
                float dt = dt_s[r0 + i];
                float4 o;
                float* op = reinterpret_cast<float*>(&o);
                #pragma unroll
                for (int j = 0; j < 4; ++j) {
                    int c = lane * 4 + j;
                    float hv = h_s[(r0 + i) * Hh + c];
                    float a = accr[i][j] + kv[i][j];
                    op[j] = (dt > 0.0f) ? (hv + dt * a * 0.125f) : hv;
                }
                *reinterpret_cast<float4*>(evolved + (row0 + r0 + i) * Hh + lane * 4) = o;
            }
        }
        __syncwarp();   // arg_s written before next stage's mm1 reads (same warp)
    }
}

// ---------------------------------------------------------------------------
// GRU update. lane owns column PAIRS: col = g*128 + 64*m + 2*lane (+t), so
// weights load as conflict-free LDS.64 feeding FFMA2 directly, and r/z/n for
// the same hidden index stay on the same lane.
// ---------------------------------------------------------------------------
#define GRU_SMEM_FLOATS 57344
__global__ void __launch_bounds__(NTHR, 1) gru_kernel(
    const float* __restrict__ evolved, const float* __restrict__ obs,
    const int* __restrict__ mask,
    const float* __restrict__ bih, const float* __restrict__ bhh,
    float* __restrict__ updated)
{
    extern __shared__ float sm[];
    float* w_s   = sm;              // 128x384 (192KB) — WihT then WhhT
    float* obs_s = sm + 49152;      // 32x128
    float* ev_s  = sm + 53248;      // 32x128

    const int tid  = threadIdx.x;
    const int lane = tid & 31;
    const int wrp  = tid >> 5;
    const int r0   = wrp * 4;
    const size_t row0 = (size_t)blockIdx.x * MT;

    {
        const float4* so = reinterpret_cast<const float4*>(obs + row0 * Ee);
        const float4* se = reinterpret_cast<const float4*>(evolved + row0 * Hh);
        float4* dobs = reinterpret_cast<float4*>(obs_s);
        float4* dev  = reinterpret_cast<float4*>(ev_s);
        #pragma unroll
        for (int t = 0; t < 4; ++t) {
            dobs[tid + t * NTHR] = so[tid + t * NTHR];
            dev[tid + t * NTHR]  = se[tid + t * NTHR];
        }
    }
    {
        const float4* src = reinterpret_cast<const float4*>(g_wihT);
        float4* dst = reinterpret_cast<float4*>(w_s);
        #pragma unroll
        for (int t = 0; t < 48; ++t) dst[tid + t * NTHR] = src[tid + t * NTHR];
    }
    __syncthreads();

    // accumulators: [row i][g*2+m] packed pairs
    u64 gi2[4][6], gh2[4][6];
    #pragma unroll
    for (int g = 0; g < 3; ++g)
        #pragma unroll
        for (int m = 0; m < 2; ++m) {
            int c = g * Hh + 64 * m + 2 * lane;
            u64 bi = pack2(__ldg(bih + c), __ldg(bih + c + 1));
            u64 bh = pack2(__ldg(bhh + c), __ldg(bhh + c + 1));
            #pragma unroll
            for (int i = 0; i < 4; ++i) { gi2[i][g * 2 + m] = bi; gh2[i][g * 2 + m] = bh; }
        }

    // gi = obs @ WihT + bih
    #pragma unroll 2
    for (int e = 0; e < Ee; e += 4) {
        float4 ov[4];
        #pragma unroll
        for (int i = 0; i < 4; ++i)
            ov[i] = *reinterpret_cast<const float4*>(obs_s + (r0 + i) * Ee + e);
        #pragma unroll
        for (int ee = 0; ee < 4; ++ee) {
            const float* wb = w_s + (e + ee) * G3H + 2 * lane;
            u64 W[6];
            #pragma unroll
            for (int g = 0; g < 3; ++g)
                #pragma unroll
                for (int m = 0; m < 2; ++m)
                    W[g * 2 + m] = *reinterpret_cast<const u64*>(wb + g * Hh + 64 * m);
            #pragma unroll
            for (int i = 0; i < 4; ++i) {
                float a = (ee == 0) ? ov[i].x : (ee == 1) ? ov[i].y
                        : (ee == 2) ? ov[i].z : ov[i].w;
                u64 aa = bcast2(a);
                #pragma unroll
                for (int q = 0; q < 6; ++q) ffma2(gi2[i][q], aa, W[q]);
            }
        }
    }
    __syncthreads();    // all warps done with WihT
    {
        const float4* src = reinterpret_cast<const float4*>(g_whhT);
        float4* dst = reinterpret_cast<float4*>(w_s);
        #pragma unroll
        for (int t = 0; t < 48; ++t) dst[tid + t * NTHR] = src[tid + t * NTHR];
    }
    __syncthreads();

    // gh = evolved @ WhhT + bhh
    #pragma unroll 2
    for (int e = 0; e < Hh; e += 4) {
        float4 ov[4];
        #pragma unroll
        for (int i = 0; i < 4; ++i)
            ov[i] = *reinterpret_cast<const float4*>(ev_s + (r0 + i) * Hh + e);
        #pragma unroll
        for (int ee = 0; ee < 4; ++ee) {
            const float* wb = w_s + (e + ee) * G3H + 2 * lane;
            u64 W[6];
            #pragma unroll
            for (int g = 0; g < 3; ++g)
                #pragma unroll
                for (int m = 0; m < 2; ++m)
                    W[g * 2 + m] = *reinterpret_cast<const u64*>(wb + g * Hh + 64 * m);
            #pragma unroll
            for (int i = 0; i < 4; ++i) {
                float a = (ee == 0) ? ov[i].x : (ee == 1) ? ov[i].y
                        : (ee == 2) ? ov[i].z : ov[i].w;
                u64 aa = bcast2(a);
                #pragma unroll
                for (int q = 0; q < 6; ++q) ffma2(gh2[i][q], aa, W[q]);
            }
        }
    }

    // gates + select
    #pragma unroll
    for (int i = 0; i < 4; ++i) {
        size_t grow = row0 + r0 + i;
        int msk = __ldg(mask + grow);
        #pragma unroll
        for (int m = 0; m < 2; ++m) {
            float ir0, ir1, iz0, iz1, in0, in1;
            float hr0, hr1, hz0, hz1, hn0, hn1;
            unpk2(gi2[i][0 + m], ir0, ir1);
            unpk2(gi2[i][2 + m], iz0, iz1);
            unpk2(gi2[i][4 + m], in0, in1);
            unpk2(gh2[i][0 + m], hr0, hr1);
            unpk2(gh2[i][2 + m], hz0, hz1);
            unpk2(gh2[i][4 + m], hn0, hn1);

            int hidx = 64 * m + 2 * lane;
            float2 ev = *reinterpret_cast<const float2*>(
                ev_s + (r0 + i) * Hh + hidx);

            float r0g = 1.0f / (1.0f + __expf(-(ir0 + hr0)));
            float z0g = 1.0f / (1.0f + __expf(-(iz0 + hz0)));
            float n0g = tanhf(in0 + r0g * hn0);
            float o0 = (msk > 0) ? ((1.0f - z0g) * n0g + z0g * ev.x) : ev.x;

            float r1g = 1.0f / (1.0f + __expf(-(ir1 + hr1)));
            float z1g = 1.0f / (1.0f + __expf(-(iz1 + hz1)));
            float n1g = tanhf(in1 + r1g * hn1);
            float o1 = (msk > 0) ? ((1.0f - z1g) * n1g + z1g * ev.y) : ev.y;

            float2 o; o.x = o0; o.y = o1;
            *reinterpret_cast<float2*>(updated + grow * Hh + hidx) = o;
        }
    }
}

// ---------------------------------------------------------------------------
extern "C" void kernel_launch(void* const* d_in, const int* in_sizes, int n_in,
                              void* d_out, int out_size)
{
    const float* hidden = (const float*)d_in[0];
    const float* dts    = (const float*)d_in[1];
    const float* obs    = (const float*)d_in[2];
    const int*   mask   = (const int*)d_in[3];
    const float* w1     = (const float*)d_in[4];
    const float* b1     = (const float*)d_in[5];
    const float* lnw    = (const float*)d_in[6];
    const float* lnb    = (const float*)d_in[7];
    const float* w2     = (const float*)d_in[8];
    const float* b2     = (const float*)d_in[9];
    const float* wih    = (const float*)d_in[10];
    const float* whh    = (const float*)d_in[11];
    const float* bih    = (const float*)d_in[12];
    const float* bhh    = (const float*)d_in[13];

    float* evolved = (float*)d_out;
    float* updated = evolved + (size_t)B_TOTAL * Hh;

    cudaFuncSetAttribute(evolve_kernel, cudaFuncAttributeMaxDynamicSharedMemorySize,
                         EV_SMEM_FLOATS * 4);
    cudaFuncSetAttribute(gru_kernel, cudaFuncAttributeMaxDynamicSharedMemorySize,
                         GRU_SMEM_FLOATS * 4);

    transpose_gru_kernel<<<(Ee * G3H + 255) / 256, 256>>>(wih, whh);
    evolve_kernel<<<B_TOTAL / MT, NTHR, EV_SMEM_FLOATS * 4>>>(
        hidden, dts, w1, b1, lnw, lnb, w2, b2, evolved);
    gru_kernel<<<B_TOTAL / MT, NTHR, GRU_SMEM_FLOATS * 4>>>(
        evolved, obs, mask, bih, bhh, updated);
}